// round 15
// baseline (speedup 1.0000x reference)
#include <cuda_runtime.h>
#include <cuda_bf16.h>
#include <math.h>
#include <stdint.h>

#define NN   4096
#define RTOT 501
#define RPAD 512
#define NLEV 5
#define CUT  16.0f              // phi treated as 0 beyond |a|>CUT (exp<4e-6)
#define NBLK 148                // persistent grid: one block per SM

// ---- device scratch (static, BSS zero-initialized; out-of-window entries of
// g_Wc/g_Wr/g_Btf and all pad columns are NEVER written -> stay exactly 0) ----
__device__ float g_Wc[NN * RPAD];
__device__ float g_Wr[NN * RPAD];
__device__ float g_T [NN * RPAD];
__device__ int   g_ic[RTOT];
__device__ int   g_ir[RTOT];
__device__ float g_D [257 * 257];
__device__ __align__(1024) float g_Atf[NN * RPAD];
__device__ __align__(1024) float g_Btf[NN * RPAD];
// global barrier state (BSS zero; cnt self-resets, phs compared by inequality)
__device__ int           g_bar_cnt;
__device__ volatile int  g_bar_phs;

__constant__ int c_off[5] = {0, 17, 50, 115, 244};
__constant__ int c_sc [5] = {8, 16, 32, 64, 128};
__constant__ int c_K  [5] = {17, 33, 65, 129, 257};

__device__ __forceinline__ uint32_t to_tf32(float v) {
    uint32_t t;
    asm("cvt.rna.tf32.f32 %0, %1;" : "=r"(t) : "f"(v));
    return t;
}

// grid-wide barrier: all NBLK blocks co-resident (1/SM) -> no deadlock
__device__ __forceinline__ void gbar() {
    __syncthreads();
    if (threadIdx.x == 0) {
        int p = g_bar_phs;
        __threadfence();
        if (atomicAdd(&g_bar_cnt, 1) == NBLK - 1) {
            g_bar_cnt = 0;
            __threadfence();
            g_bar_phs = p + 1;
        } else {
            while (g_bar_phs == p) { }
        }
        __threadfence();
    }
    __syncthreads();
}

__device__ __forceinline__ int nearest_sorted(const float* __restrict__ x, float tgt) {
    int lo = 0, hi = NN;
    while (lo < hi) { int mid = (lo + hi) >> 1; if (x[mid] < tgt) lo = mid + 1; else hi = mid; }
    if (lo == 0)  return 0;
    if (lo == NN) return NN - 1;
    float d1 = fabsf(x[lo - 1] - tgt);
    float d2 = fabsf(x[lo] - tgt);
    return (d1 <= d2) ? (lo - 1) : lo;
}

// ---------------------------------------------------------------------------
// ONE persistent kernel: idx + w, then per level D -> T, with global barriers.
// ---------------------------------------------------------------------------
__global__ __launch_bounds__(256) void k_prep(const float* __restrict__ img,
                                              const float* __restrict__ xc,
                                              const float* __restrict__ xr) {
    __shared__ float Trow[256];
    const int bid  = blockIdx.x;
    const int tid  = threadIdx.x;
    const int lane = tid & 31;

    // ---- phase 0a: nearest indices ----
    for (int col = bid * 256 + tid; col < RTOT; col += NBLK * 256) {
        int l = (col < 17) ? 0 : (col < 50) ? 1 : (col < 115) ? 2 : (col < 244) ? 3 : 4;
        int m = (col - c_off[l]) - c_sc[l];
        float tgt = (float)m / (float)c_sc[l];
        g_ic[col] = nearest_sorted(xc, tgt);
        g_ir[col] = nearest_sorted(xr, tgt);
    }

    // ---- phase 0b: windowed factors (warp per (n,side) unit) ----
    {
        const int gwarp  = bid * 8 + (tid >> 5);
        const int nwarps = NBLK * 8;
        for (int u = gwarp; u < 2 * NN; u += nwarps) {
            const int n = u >> 1, side = u & 1;
            const float x = side ? xr[n] : xc[n];
            float spv = 0.0f;
            if (lane < 5) spv = sinpif((float)c_sc[lane] * x);
            const size_t rowb = (size_t)n * RPAD;
#pragma unroll
            for (int l = 0; l < 5; ++l) {
                const int s = c_sc[l], K = c_K[l], off = c_off[l];
                const float fs = (float)s;
                const float sp = __shfl_sync(0xffffffffu, spv, l);
                int jlo = (int)floorf(fs * x - CUT) + s - 1;
                int jhi = (int)ceilf (fs * x + CUT) + s + 1;
                if (jlo < 0) jlo = 0;
                if (jhi > K - 1) jhi = K - 1;
                for (int j = jlo + lane; j <= jhi; j += 32) {
                    int m = j - s;
                    float a = fs * x - (float)m;
                    float v;
                    if (a == 0.0f) v = 1.0f;
                    else {
                        float sgn = (m & 1) ? -sp : sp;
                        v = sgn * __expf(a * a * (-1.0f / 20.48f))
                                * __fdividef(1.0f, 3.14159265358979323846f * a);
                    }
                    int kg = off + j;
                    if (side) {
                        g_Wr[rowb + kg]  = v;
                        g_Btf[rowb + kg] = __uint_as_float(to_tf32(v));
                    } else {
                        g_Wc[rowb + kg]  = v;
                    }
                }
            }
        }
    }
    gbar();

    // ---- per-level D then T ----
    for (int l = 0; l < NLEV; ++l) {
        const int off = c_off[l], K = c_K[l], s = c_sc[l];
        const int thresh_on = (l > 0);

        // D phase: tiles = (a in [0,K)) x (b-chunks of 256)
        {
            const int bch = (K + 255) / 256;
            const int ntiles = K * bch;
            for (int t = bid; t < ntiles; t += NBLK) {
                const int a  = t / bch;
                const int bc = t % bch;
                const int ica = g_ic[off + a];
                for (int r = tid; r < off; r += 256)
                    Trow[r] = g_T[(size_t)ica * RPAD + r];
                __syncthreads();
                const int b = bc * 256 + tid;
                if (b < K) {
                    const int irb = g_ir[off + b];
                    const float* wr = &g_Wr[(size_t)irb * RPAD];
                    float u = 0.0f;
                    if (off > 0) {
                        float x = xr[irb];
#pragma unroll
                        for (int ll = 0; ll < 4; ++ll) {
                            if (c_off[ll] >= off) break;
                            int ss = c_sc[ll];
                            float fs = (float)ss;
                            int jlo = (int)floorf(fs * x - CUT) + ss - 1;
                            int jhi = (int)ceilf (fs * x + CUT) + ss + 1;
                            if (jlo < 0) jlo = 0;
                            if (jhi > c_K[ll] - 1) jhi = c_K[ll] - 1;
                            int base = c_off[ll];
                            for (int j = jlo; j <= jhi; ++j)
                                u += Trow[base + j] * wr[base + j];
                        }
                    }
                    float d = img[(size_t)ica * NN + irb] - u;
                    if (thresh_on && fabsf(d) <= 0.01f) d = 0.0f;
                    g_D[a * K + b] = d;
                }
                __syncthreads();   // Trow reuse safety
            }
        }
        gbar();

        // T phase: tiles = (b-chunks of 64) x (n-chunks of 4); thread (64,4)
        {
            const int bch = (K + 63) / 64;
            const int ntiles = bch * (NN / 4);
            const int tx = tid & 63, ty = tid >> 6;
            for (int t = bid; t < ntiles; t += NBLK) {
                const int bc = t % bch;
                const int nc = t / bch;
                const int b = bc * 64 + tx;
                const int n = nc * 4 + ty;
                if (b < K) {
                    float fs = (float)s, x = xc[n];
                    int alo = (int)floorf(fs * x - CUT) + s - 1;
                    int ahi = (int)ceilf (fs * x + CUT) + s + 1;
                    if (alo < 0) alo = 0;
                    if (ahi > K - 1) ahi = K - 1;
                    const float* wc = &g_Wc[(size_t)n * RPAD + off];
                    float acc = 0.0f;
                    for (int a = alo; a <= ahi; ++a)
                        acc += wc[a] * g_D[a * K + b];
                    size_t idx = (size_t)n * RPAD + off + b;
                    g_T[idx] = acc;
                    g_Atf[idx] = __uint_as_float(to_tf32(acc));
                }
            }
        }
        gbar();
    }
}

// ---------------------------------------------------------------------------
// tf32 GEMM with per-tile k-window (unchanged from the 173.7us version).
// ---------------------------------------------------------------------------
#define TSTAGE 16384
#define TGSMEM (2 * TSTAGE + 256)

__device__ __forceinline__ uint32_t soff(uint32_t r, uint32_t k) {
    return r * 64 + ((((k >> 2) ^ ((r >> 1) & 3)) & 3) << 4) + ((k & 3) << 2);
}
__device__ __forceinline__ uint32_t smem_u32(const void* p) {
    uint32_t a;
    asm("{ .reg .u64 t; cvta.to.shared.u64 t, %1; cvt.u32.u64 %0, t; }"
        : "=r"(a) : "l"(p));
    return a;
}
__device__ __forceinline__ void cp16(uint32_t s, const void* g) {
    asm volatile("cp.async.cg.shared.global [%0], [%1], 16;" :: "r"(s), "l"(g));
}
__device__ __forceinline__ void mma_tf32(float& d0, float& d1, float& d2, float& d3,
                                         uint32_t a0, uint32_t a1, uint32_t a2,
                                         uint32_t a3, uint32_t b0, uint32_t b1) {
    asm volatile(
        "mma.sync.aligned.m16n8k8.row.col.f32.tf32.tf32.f32 "
        "{%0,%1,%2,%3}, {%4,%5,%6,%7}, {%8,%9}, {%0,%1,%2,%3};"
        : "+f"(d0), "+f"(d1), "+f"(d2), "+f"(d3)
        : "r"(a0), "r"(a1), "r"(a2), "r"(a3), "r"(b0), "r"(b1));
}

__global__ __launch_bounds__(256, 2) void k_gemm_tf32(float* __restrict__ C,
                                                      const float* __restrict__ xr) {
    extern __shared__ char smem[];
    const uint32_t sb = smem_u32(smem);
    int* s_list = (int*)(smem + 2 * TSTAGE);
    const int tid  = threadIdx.x;
    const int wid  = tid >> 5, lane = tid & 31;
    const int n0   = blockIdx.y * 128;
    const int m0   = blockIdx.x * 128;
    const int wm   = (wid >> 2) * 64;
    const int wn   = (wid & 3) * 32;

    if (tid == 0) {
        float xmin = xr[m0], xmax = xr[m0 + 127];
        uint32_t mask = 0;
#pragma unroll
        for (int l = 0; l < 5; ++l) {
            int s = c_sc[l];
            float fs = (float)s;
            int lo = c_off[l] + s + (int)floorf(fs * xmin - CUT) - 1;
            int hi = c_off[l] + s + (int)ceilf (fs * xmax + CUT) + 1;
            if (lo < c_off[l]) lo = c_off[l];
            if (hi > c_off[l] + c_K[l] - 1) hi = c_off[l] + c_K[l] - 1;
            if (lo > hi) continue;
            for (int b = (lo >> 4); b <= (hi >> 4); ++b) mask |= (1u << b);
        }
        int nb = 0;
        while (mask) { int b = __ffs(mask) - 1; mask &= mask - 1; s_list[1 + nb++] = b; }
        s_list[0] = nb;
    }
    __syncthreads();
    const int nb = s_list[0];

    float acc[4][4][4];
#pragma unroll
    for (int i = 0; i < 4; ++i)
#pragma unroll
        for (int j = 0; j < 4; ++j)
#pragma unroll
            for (int q = 0; q < 4; ++q) acc[i][j][q] = 0.0f;

    const float* Ab = g_Atf + (size_t)n0 * RPAD;
    const float* Bb = g_Btf + (size_t)m0 * RPAD;

    auto load_chunk = [&](int blk, int stage) {
        const int k0 = blk * 16;
        const uint32_t stb = sb + stage * TSTAGE;
#pragma unroll
        for (int i = 0; i < 4; ++i) {
            int u   = tid + i * 256;
            int arr = u >> 9, rem = u & 511;
            int row = rem >> 2, cq = rem & 3;
            const float* gp = (arr ? Bb : Ab) + (size_t)row * RPAD + k0 + cq * 4;
            cp16(stb + arr * 8192 + row * 64 + (((cq ^ ((row >> 1) & 3)) & 3) << 4), gp);
        }
        asm volatile("cp.async.commit_group;" ::: "memory");
    };

    load_chunk(s_list[1], 0);
    load_chunk(s_list[2], 1);

    const int aq = lane >> 2;
    const int ak = lane & 3;

    for (int c = 0; c < nb; ++c) {
        const int stage = c & 1;
        if (c < nb - 1) asm volatile("cp.async.wait_group 1;" ::: "memory");
        else            asm volatile("cp.async.wait_group 0;" ::: "memory");
        __syncthreads();

        const char* sA = smem + stage * TSTAGE;
        const char* sB = sA + 8192;

#pragma unroll
        for (int ks = 0; ks < 2; ++ks) {
            const int kb = ks * 8;
            uint32_t a[4][4];
#pragma unroll
            for (int mi = 0; mi < 4; ++mi) {
                int r = wm + mi * 16 + aq;
                a[mi][0] = *(const uint32_t*)(sA + soff(r,     kb + ak));
                a[mi][1] = *(const uint32_t*)(sA + soff(r + 8, kb + ak));
                a[mi][2] = *(const uint32_t*)(sA + soff(r,     kb + ak + 4));
                a[mi][3] = *(const uint32_t*)(sA + soff(r + 8, kb + ak + 4));
            }
            uint32_t b[4][2];
#pragma unroll
            for (int nj = 0; nj < 4; ++nj) {
                int r = wn + nj * 8 + aq;
                b[nj][0] = *(const uint32_t*)(sB + soff(r, kb + ak));
                b[nj][1] = *(const uint32_t*)(sB + soff(r, kb + ak + 4));
            }
#pragma unroll
            for (int mi = 0; mi < 4; ++mi)
#pragma unroll
                for (int nj = 0; nj < 4; ++nj)
                    mma_tf32(acc[mi][nj][0], acc[mi][nj][1],
                             acc[mi][nj][2], acc[mi][nj][3],
                             a[mi][0], a[mi][1], a[mi][2], a[mi][3],
                             b[nj][0], b[nj][1]);
        }

        __syncthreads();
        if (c + 2 < nb) load_chunk(s_list[1 + c + 2], stage);
    }

#pragma unroll
    for (int mi = 0; mi < 4; ++mi) {
        int row = n0 + wm + mi * 16 + (lane >> 2);
#pragma unroll
        for (int nj = 0; nj < 4; ++nj) {
            int col = m0 + wn + nj * 8 + (lane & 3) * 2;
            float2* p0 = (float2*)(C + (size_t)row * NN + col);
            float2* p1 = (float2*)(C + (size_t)(row + 8) * NN + col);
            *p0 = make_float2(acc[mi][nj][0], acc[mi][nj][1]);
            *p1 = make_float2(acc[mi][nj][2], acc[mi][nj][3]);
        }
    }
}

// ---------------------------------------------------------------------------
extern "C" void kernel_launch(void* const* d_in, const int* in_sizes, int n_in,
                              void* d_out, int out_size) {
    const float* img = (const float*)d_in[0];
    const float* xc  = (const float*)d_in[1];
    const float* xr  = (const float*)d_in[2];
    float* out = (float*)d_out;

    (void)in_sizes; (void)n_in; (void)out_size;

    cudaFuncSetAttribute(k_gemm_tf32, cudaFuncAttributeMaxDynamicSharedMemorySize,
                         TGSMEM);

    // 1. ONE persistent prep kernel (idx + factors + all D/T levels)
    k_prep<<<NBLK, 256>>>(img, xc, xr);

    // 2. out = T * Wr^T, tf32 tensor cores + per-tile k-window
    dim3 gg(NN / 128, NN / 128);   // (32, 32)
    k_gemm_tf32<<<gg, 256, TGSMEM>>>(out, xr);
}

// round 16
// speedup vs baseline: 1.9584x; 1.9584x over previous
#include <cuda_runtime.h>
#include <cuda_bf16.h>
#include <math.h>
#include <stdint.h>

#define NN   4096
#define RTOT 501
#define RPAD 512
#define NLEV 5
#define CUT  16.0f              // phi exactly 0 beyond |a|>CUT (exp<4e-6)
#define NBLK 148                // persistent chain grid (<= SM count)

// ---- device scratch (static, BSS zero-initialized) ----
__device__ float g_Wc[NN * RPAD];
__device__ float g_Wr[NN * RPAD];
__device__ float g_T [NN * RPAD];      // only ic-rows are ever written/read
__device__ int   g_ic[RTOT];
__device__ int   g_ir[RTOT];
__device__ float g_Dall[88293];        // per-level D, offsets c_doff
__device__ __align__(1024) float g_Atf[NN * RPAD];
__device__ __align__(1024) float g_Btf[NN * RPAD];
// global barrier state (cnt self-resets; phs compared by inequality)
__device__ int           g_bar_cnt;
__device__ volatile int  g_bar_phs;

__constant__ int c_off [5] = {0, 17, 50, 115, 244};
__constant__ int c_sc  [5] = {8, 16, 32, 64, 128};
__constant__ int c_K   [5] = {17, 33, 65, 129, 257};
__constant__ int c_doff[5] = {0, 289, 1378, 5603, 22244};
// bigT chunk tables: 12 chunks of 64 columns across the 5 levels
__constant__ int c_clvl[12] = {0, 1, 2, 2, 3, 3, 3, 4, 4, 4, 4, 4};
__constant__ int c_cbc [12] = {0, 0, 0, 1, 0, 1, 2, 0, 1, 2, 3, 4};

// ---------------------------------------------------------------------------
__device__ __forceinline__ float phi_f(float a) {
    float t = 3.14159265358979323846f * a;
    if (t == 0.0f) return 1.0f;
    float a2 = a * a;
    if (a2 > CUT * CUT) return 0.0f;
    return __fdividef(sinpif(a), t) * __expf(a2 * (-1.0f / 20.48f));
}
__device__ __forceinline__ uint32_t to_tf32(float v) {
    uint32_t t;
    asm("cvt.rna.tf32.f32 %0, %1;" : "=r"(t) : "f"(v));
    return t;
}

// Dense factor fill (R13-proven): Wc, Wr, tf32(B); zero pads everywhere.
__global__ void k_compute_w(const float* __restrict__ xc,
                            const float* __restrict__ xr) {
    int idx = blockIdx.x * blockDim.x + threadIdx.x;
    if (idx >= NN * RPAD) return;
    int n   = idx >> 9;
    int col = idx & (RPAD - 1);
    if (col >= RTOT) {
        g_Wc[idx] = 0.0f; g_Wr[idx] = 0.0f;
        g_Atf[idx] = 0.0f; g_Btf[idx] = 0.0f;
        return;
    }
    int l = (col < 17) ? 0 : (col < 50) ? 1 : (col < 115) ? 2 : (col < 244) ? 3 : 4;
    int off = c_off[l], s = c_sc[l];
    int m = (col - off) - s;
    float fs = (float)s, fm = (float)m;
    float wr = phi_f(fs * xr[n] - fm);
    g_Wc[idx] = phi_f(fs * xc[n] - fm);
    g_Wr[idx] = wr;
    g_Btf[idx] = __uint_as_float(to_tf32(wr));
}

__device__ __forceinline__ int nearest_sorted(const float* __restrict__ x, float tgt) {
    int lo = 0, hi = NN;
    while (lo < hi) { int mid = (lo + hi) >> 1; if (x[mid] < tgt) lo = mid + 1; else hi = mid; }
    if (lo == 0)  return 0;
    if (lo == NN) return NN - 1;
    float d1 = fabsf(x[lo - 1] - tgt);
    float d2 = fabsf(x[lo] - tgt);
    return (d1 <= d2) ? (lo - 1) : lo;
}

// grid-wide barrier (NBLK co-resident blocks)
__device__ __forceinline__ void gbar() {
    __syncthreads();
    if (threadIdx.x == 0) {
        int p = g_bar_phs;
        __threadfence();
        if (atomicAdd(&g_bar_cnt, 1) == NBLK - 1) {
            g_bar_cnt = 0;
            __threadfence();
            g_bar_phs = p + 1;
        } else {
            while (g_bar_phs == p) { }
        }
        __threadfence();
    }
    __syncthreads();
}

// ---------------------------------------------------------------------------
// Persistent CHAIN kernel — only the tiny serial work:
//   idx -> D0 -> t0 -> D1 -> t1 -> D2 -> t2 -> D3 -> t3 -> D4
// t_l computes T ONLY for the 501 ic-rows (what later D's read).
// ---------------------------------------------------------------------------
__global__ __launch_bounds__(256) void k_chain(const float* __restrict__ img,
                                               const float* __restrict__ xc,
                                               const float* __restrict__ xr) {
    __shared__ float Trow[256];
    const int bid = blockIdx.x;
    const int tid = threadIdx.x;

    // ---- idx ----
    for (int col = bid * 256 + tid; col < RTOT; col += NBLK * 256) {
        int l = (col < 17) ? 0 : (col < 50) ? 1 : (col < 115) ? 2 : (col < 244) ? 3 : 4;
        int m = (col - c_off[l]) - c_sc[l];
        float tgt = (float)m / (float)c_sc[l];
        g_ic[col] = nearest_sorted(xc, tgt);
        g_ir[col] = nearest_sorted(xr, tgt);
    }
    gbar();

    for (int l = 0; l < NLEV; ++l) {
        const int off = c_off[l], K = c_K[l];
        const float* Dprev = g_Dall;            // (unused name clarity)
        float* Dl = g_Dall + c_doff[l];
        (void)Dprev;

        // ---- D phase: tiles = (a) x (b-chunks of 256) ----
        {
            const int bch = (K + 255) / 256;
            const int ntiles = K * bch;
            for (int t = bid; t < ntiles; t += NBLK) {
                const int a  = t / bch;
                const int bc = t % bch;
                const int ica = g_ic[off + a];
                for (int r = tid; r < off; r += 256)
                    Trow[r] = g_T[(size_t)ica * RPAD + r];
                __syncthreads();
                const int b = bc * 256 + tid;
                if (b < K) {
                    const int irb = g_ir[off + b];
                    const float* wr = &g_Wr[(size_t)irb * RPAD];
                    float u = 0.0f;
                    if (off > 0) {
                        float x = xr[irb];
#pragma unroll
                        for (int ll = 0; ll < 4; ++ll) {
                            if (c_off[ll] >= off) break;
                            int ss = c_sc[ll];
                            float fs = (float)ss;
                            int jlo = (int)floorf(fs * x - CUT) + ss - 1;
                            int jhi = (int)ceilf (fs * x + CUT) + ss + 1;
                            if (jlo < 0) jlo = 0;
                            if (jhi > c_K[ll] - 1) jhi = c_K[ll] - 1;
                            int base = c_off[ll];
                            for (int j = jlo; j <= jhi; ++j)
                                u += Trow[base + j] * wr[base + j];
                        }
                    }
                    float d = img[(size_t)ica * NN + irb] - u;
                    if (l > 0 && fabsf(d) <= 0.01f) d = 0.0f;
                    Dl[a * K + b] = d;
                }
                __syncthreads();
            }
        }
        gbar();

        // ---- t phase (skip after last level): T at ic-rows only ----
        if (l < NLEV - 1) {
            const int s = c_sc[l];
            const int bch = (K + 255) / 256;
            const int ntiles = RTOT * bch;
            for (int t = bid; t < ntiles; t += NBLK) {
                const int p  = t / bch;
                const int bc = t % bch;
                const int row = g_ic[p];        // duplicates write identical bits
                const int b = bc * 256 + tid;
                if (b < K) {
                    float fs = (float)s, x = xc[row];
                    int alo = (int)floorf(fs * x - CUT) + s - 1;
                    int ahi = (int)ceilf (fs * x + CUT) + s + 1;
                    if (alo < 0) alo = 0;
                    if (ahi > K - 1) ahi = K - 1;
                    const float* wc = &g_Wc[(size_t)row * RPAD + off];
                    float acc = 0.0f;
                    for (int a = alo; a <= ahi; ++a)
                        acc += wc[a] * Dl[a * K + b];
                    g_T[(size_t)row * RPAD + off + b] = acc;
                }
            }
            gbar();
        }
    }
}

// ---------------------------------------------------------------------------
// bigT: full A operand tf32(T[n, :]) for all n, all levels — fat parallel
// launch (off the critical chain). block (64,4), grid (12, NN/4).
// ---------------------------------------------------------------------------
__global__ void k_bigT(const float* __restrict__ xc) {
    const int cx = blockIdx.x;
    const int l  = c_clvl[cx], bc = c_cbc[cx];
    const int off = c_off[l], K = c_K[l], s = c_sc[l];
    const int b = bc * 64 + (threadIdx.x & 63);
    const int n = blockIdx.y * 4 + (threadIdx.x >> 6);
    if (b >= K) return;
    const float* Dl = g_Dall + c_doff[l];
    float fs = (float)s, x = xc[n];
    int alo = (int)floorf(fs * x - CUT) + s - 1;
    int ahi = (int)ceilf (fs * x + CUT) + s + 1;
    if (alo < 0) alo = 0;
    if (ahi > K - 1) ahi = K - 1;
    const float* wc = &g_Wc[(size_t)n * RPAD + off];
    float acc = 0.0f;
    for (int a = alo; a <= ahi; ++a)
        acc += wc[a] * Dl[a * K + b];
    g_Atf[(size_t)n * RPAD + off + b] = __uint_as_float(to_tf32(acc));
}

// ---------------------------------------------------------------------------
// tf32 GEMM with per-tile k-window (byte-identical to the 173.7us version).
// ---------------------------------------------------------------------------
#define TSTAGE 16384
#define TGSMEM (2 * TSTAGE + 256)

__device__ __forceinline__ uint32_t soff(uint32_t r, uint32_t k) {
    return r * 64 + ((((k >> 2) ^ ((r >> 1) & 3)) & 3) << 4) + ((k & 3) << 2);
}
__device__ __forceinline__ uint32_t smem_u32(const void* p) {
    uint32_t a;
    asm("{ .reg .u64 t; cvta.to.shared.u64 t, %1; cvt.u32.u64 %0, t; }"
        : "=r"(a) : "l"(p));
    return a;
}
__device__ __forceinline__ void cp16(uint32_t s, const void* g) {
    asm volatile("cp.async.cg.shared.global [%0], [%1], 16;" :: "r"(s), "l"(g));
}
__device__ __forceinline__ void mma_tf32(float& d0, float& d1, float& d2, float& d3,
                                         uint32_t a0, uint32_t a1, uint32_t a2,
                                         uint32_t a3, uint32_t b0, uint32_t b1) {
    asm volatile(
        "mma.sync.aligned.m16n8k8.row.col.f32.tf32.tf32.f32 "
        "{%0,%1,%2,%3}, {%4,%5,%6,%7}, {%8,%9}, {%0,%1,%2,%3};"
        : "+f"(d0), "+f"(d1), "+f"(d2), "+f"(d3)
        : "r"(a0), "r"(a1), "r"(a2), "r"(a3), "r"(b0), "r"(b1));
}

__global__ __launch_bounds__(256, 2) void k_gemm_tf32(float* __restrict__ C,
                                                      const float* __restrict__ xr) {
    extern __shared__ char smem[];
    const uint32_t sb = smem_u32(smem);
    int* s_list = (int*)(smem + 2 * TSTAGE);
    const int tid  = threadIdx.x;
    const int wid  = tid >> 5, lane = tid & 31;
    const int n0   = blockIdx.y * 128;
    const int m0   = blockIdx.x * 128;
    const int wm   = (wid >> 2) * 64;
    const int wn   = (wid & 3) * 32;

    if (tid == 0) {
        float xmin = xr[m0], xmax = xr[m0 + 127];
        uint32_t mask = 0;
#pragma unroll
        for (int l = 0; l < 5; ++l) {
            int s = c_sc[l];
            float fs = (float)s;
            int lo = c_off[l] + s + (int)floorf(fs * xmin - CUT) - 1;
            int hi = c_off[l] + s + (int)ceilf (fs * xmax + CUT) + 1;
            if (lo < c_off[l]) lo = c_off[l];
            if (hi > c_off[l] + c_K[l] - 1) hi = c_off[l] + c_K[l] - 1;
            if (lo > hi) continue;
            for (int b = (lo >> 4); b <= (hi >> 4); ++b) mask |= (1u << b);
        }
        int nb = 0;
        while (mask) { int b = __ffs(mask) - 1; mask &= mask - 1; s_list[1 + nb++] = b; }
        s_list[0] = nb;
    }
    __syncthreads();
    const int nb = s_list[0];

    float acc[4][4][4];
#pragma unroll
    for (int i = 0; i < 4; ++i)
#pragma unroll
        for (int j = 0; j < 4; ++j)
#pragma unroll
            for (int q = 0; q < 4; ++q) acc[i][j][q] = 0.0f;

    const float* Ab = g_Atf + (size_t)n0 * RPAD;
    const float* Bb = g_Btf + (size_t)m0 * RPAD;

    auto load_chunk = [&](int blk, int stage) {
        const int k0 = blk * 16;
        const uint32_t stb = sb + stage * TSTAGE;
#pragma unroll
        for (int i = 0; i < 4; ++i) {
            int u   = tid + i * 256;
            int arr = u >> 9, rem = u & 511;
            int row = rem >> 2, cq = rem & 3;
            const float* gp = (arr ? Bb : Ab) + (size_t)row * RPAD + k0 + cq * 4;
            cp16(stb + arr * 8192 + row * 64 + (((cq ^ ((row >> 1) & 3)) & 3) << 4), gp);
        }
        asm volatile("cp.async.commit_group;" ::: "memory");
    };

    load_chunk(s_list[1], 0);
    load_chunk(s_list[2], 1);

    const int aq = lane >> 2;
    const int ak = lane & 3;

    for (int c = 0; c < nb; ++c) {
        const int stage = c & 1;
        if (c < nb - 1) asm volatile("cp.async.wait_group 1;" ::: "memory");
        else            asm volatile("cp.async.wait_group 0;" ::: "memory");
        __syncthreads();

        const char* sA = smem + stage * TSTAGE;
        const char* sB = sA + 8192;

#pragma unroll
        for (int ks = 0; ks < 2; ++ks) {
            const int kb = ks * 8;
            uint32_t a[4][4];
#pragma unroll
            for (int mi = 0; mi < 4; ++mi) {
                int r = wm + mi * 16 + aq;
                a[mi][0] = *(const uint32_t*)(sA + soff(r,     kb + ak));
                a[mi][1] = *(const uint32_t*)(sA + soff(r + 8, kb + ak));
                a[mi][2] = *(const uint32_t*)(sA + soff(r,     kb + ak + 4));
                a[mi][3] = *(const uint32_t*)(sA + soff(r + 8, kb + ak + 4));
            }
            uint32_t b[4][2];
#pragma unroll
            for (int nj = 0; nj < 4; ++nj) {
                int r = wn + nj * 8 + aq;
                b[nj][0] = *(const uint32_t*)(sB + soff(r, kb + ak));
                b[nj][1] = *(const uint32_t*)(sB + soff(r, kb + ak + 4));
            }
#pragma unroll
            for (int mi = 0; mi < 4; ++mi)
#pragma unroll
                for (int nj = 0; nj < 4; ++nj)
                    mma_tf32(acc[mi][nj][0], acc[mi][nj][1],
                             acc[mi][nj][2], acc[mi][nj][3],
                             a[mi][0], a[mi][1], a[mi][2], a[mi][3],
                             b[nj][0], b[nj][1]);
        }

        __syncthreads();
        if (c + 2 < nb) load_chunk(s_list[1 + c + 2], stage);
    }

#pragma unroll
    for (int mi = 0; mi < 4; ++mi) {
        int row = n0 + wm + mi * 16 + (lane >> 2);
#pragma unroll
        for (int nj = 0; nj < 4; ++nj) {
            int col = m0 + wn + nj * 8 + (lane & 3) * 2;
            float2* p0 = (float2*)(C + (size_t)row * NN + col);
            float2* p1 = (float2*)(C + (size_t)(row + 8) * NN + col);
            *p0 = make_float2(acc[mi][nj][0], acc[mi][nj][1]);
            *p1 = make_float2(acc[mi][nj][2], acc[mi][nj][3]);
        }
    }
}

// ---------------------------------------------------------------------------
extern "C" void kernel_launch(void* const* d_in, const int* in_sizes, int n_in,
                              void* d_out, int out_size) {
    const float* img = (const float*)d_in[0];
    const float* xc  = (const float*)d_in[1];
    const float* xr  = (const float*)d_in[2];
    float* out = (float*)d_out;

    (void)in_sizes; (void)n_in; (void)out_size;

    cudaFuncSetAttribute(k_gemm_tf32, cudaFuncAttributeMaxDynamicSharedMemorySize,
                         TGSMEM);

    // 1. dense factors (+ tf32 B)
    k_compute_w<<<(NN * RPAD) / 256, 256>>>(xc, xr);
    // 2. persistent serial chain: idx + all D levels + ic-row T slices
    k_chain<<<NBLK, 256>>>(img, xc, xr);
    // 3. fat parallel A-operand build (all rows, all levels)
    k_bigT<<<dim3(12, NN / 4), 256>>>(xc);
    // 4. GEMM
    dim3 gg(NN / 128, NN / 128);
    k_gemm_tf32<<<gg, 256, TGSMEM>>>(out, xr);
}

// round 17
// speedup vs baseline: 2.3707x; 1.2105x over previous
#include <cuda_runtime.h>
#include <cuda_bf16.h>
#include <math.h>
#include <stdint.h>

#define NN   4096
#define RTOT 501
#define RPAD 512
#define NLEV 5
#define CUT  16.0f              // phi exactly 0 beyond |a|>CUT (exp<4e-6)

// ---- device scratch (static, BSS zero-initialized; pads and out-of-window
// entries are NEVER written and stay exactly 0 across replays) ----
__device__ float g_Wc[NN * RPAD];      // dense (s1) + ic-rows (s0, same bits)
__device__ float g_Wr[NN * RPAD];      // ONLY ir-rows ever written (s0)
__device__ float g_T [NN * RPAD];      // ONLY ic-rows ever written (s0)
__device__ int   g_ic[RTOT];
__device__ int   g_ir[RTOT];
__device__ float g_Dall[88293];        // per-level D, offsets c_doff
__device__ __align__(1024) float g_Atf[NN * RPAD];
__device__ __align__(1024) float g_Btf[NN * RPAD];

__constant__ int c_off [5] = {0, 17, 50, 115, 244};
__constant__ int c_sc  [5] = {8, 16, 32, 64, 128};
__constant__ int c_K   [5] = {17, 33, 65, 129, 257};
__constant__ int c_doff[5] = {0, 289, 1378, 5603, 22244};

// ---------------------------------------------------------------------------
__device__ __forceinline__ float phi_f(float a) {
    float t = 3.14159265358979323846f * a;
    if (t == 0.0f) return 1.0f;
    float a2 = a * a;
    if (a2 > CUT * CUT) return 0.0f;
    return __fdividef(sinpif(a), t) * __expf(a2 * (-1.0f / 20.48f));
}
__device__ __forceinline__ uint32_t to_tf32(float v) {
    uint32_t t;
    asm("cvt.rna.tf32.f32 %0, %1;" : "=r"(t) : "f"(v));
    return t;
}

__device__ __forceinline__ int nearest_sorted(const float* __restrict__ x, float tgt) {
    int lo = 0, hi = NN;
    while (lo < hi) { int mid = (lo + hi) >> 1; if (x[mid] < tgt) lo = mid + 1; else hi = mid; }
    if (lo == 0)  return 0;
    if (lo == NN) return NN - 1;
    float d1 = fabsf(x[lo - 1] - tgt);
    float d2 = fabsf(x[lo] - tgt);
    return (d1 <= d2) ? (lo - 1) : lo;
}

__global__ void k_idx(const float* __restrict__ xc, const float* __restrict__ xr) {
    int col = blockIdx.x * blockDim.x + threadIdx.x;
    if (col >= RTOT) return;
    int l = (col < 17) ? 0 : (col < 50) ? 1 : (col < 115) ? 2 : (col < 244) ? 3 : 4;
    int m = (col - c_off[l]) - c_sc[l];
    float tgt = (float)m / (float)c_sc[l];
    g_ic[col] = nearest_sorted(xc, tgt);
    g_ir[col] = nearest_sorted(xr, tgt);
}

// Small factor fill: only the 1002 sample rows (warp per (p,side) unit).
__global__ void k_smallw(const float* __restrict__ xc, const float* __restrict__ xr) {
    int u = blockIdx.x * 8 + (threadIdx.x >> 5);
    if (u >= 2 * RTOT) return;
    int lane = threadIdx.x & 31;
    int p = u >> 1, side = u & 1;
    int row = side ? g_ir[p] : g_ic[p];
    float x = side ? xr[row] : xc[row];
    size_t rowb = (size_t)row * RPAD;
#pragma unroll
    for (int l = 0; l < 5; ++l) {
        int s = c_sc[l], K = c_K[l], off = c_off[l];
        float fs = (float)s;
        int jlo = (int)floorf(fs * x - CUT) + s - 1;
        int jhi = (int)ceilf (fs * x + CUT) + s + 1;
        if (jlo < 0) jlo = 0;
        if (jhi > K - 1) jhi = K - 1;
        for (int j = jlo + lane; j <= jhi; j += 32) {
            float v = phi_f(fs * x - (float)(j - s));
            if (side) g_Wr[rowb + off + j] = v;
            else      g_Wc[rowb + off + j] = v;
        }
    }
}

// Dense factors (stream s1): Wc dense + tf32(B) dense. No pad writes (BSS 0).
__global__ void k_w_dense(const float* __restrict__ xc, const float* __restrict__ xr) {
    int idx = blockIdx.x * blockDim.x + threadIdx.x;
    if (idx >= NN * RPAD) return;
    int n   = idx >> 9;
    int col = idx & (RPAD - 1);
    if (col >= RTOT) return;
    int l = (col < 17) ? 0 : (col < 50) ? 1 : (col < 115) ? 2 : (col < 244) ? 3 : 4;
    int off = c_off[l], s = c_sc[l];
    int m = (col - off) - s;
    float fs = (float)s, fm = (float)m;
    g_Wc[idx]  = phi_f(fs * xc[n] - fm);
    g_Btf[idx] = __uint_as_float(to_tf32(phi_f(fs * xr[n] - fm)));
}

// D level: grid ((K+255)/256, K). u-dot windowed per previous level.
__global__ void k_D(const float* __restrict__ img, const float* __restrict__ xr,
                    int l) {
    __shared__ float Trow[256];
    const int off = c_off[l], K = c_K[l];
    float* Dl = g_Dall + c_doff[l];
    int a   = blockIdx.y;
    int b   = blockIdx.x * blockDim.x + threadIdx.x;
    int ica = g_ic[off + a];
    for (int r = threadIdx.x; r < off; r += blockDim.x)
        Trow[r] = g_T[(size_t)ica * RPAD + r];
    __syncthreads();
    if (b >= K) return;
    int irb = g_ir[off + b];
    const float* wr = &g_Wr[(size_t)irb * RPAD];
    float u = 0.0f;
    if (off > 0) {
        float x = xr[irb];
#pragma unroll
        for (int ll = 0; ll < 4; ++ll) {
            if (c_off[ll] >= off) break;
            int ss = c_sc[ll];
            float fs = (float)ss;
            int jlo = (int)floorf(fs * x - CUT) + ss - 1;
            int jhi = (int)ceilf (fs * x + CUT) + ss + 1;
            if (jlo < 0) jlo = 0;
            if (jhi > c_K[ll] - 1) jhi = c_K[ll] - 1;
            int base = c_off[ll];
            for (int j = jlo; j <= jhi; ++j)
                u += Trow[base + j] * wr[base + j];
        }
    }
    float d = img[(size_t)ica * NN + irb] - u;
    if (l > 0 && fabsf(d) <= 0.01f) d = 0.0f;
    Dl[a * K + b] = d;
}

// Small T: only ic-rows (what the next D reads). grid ((K+255)/256, RTOT).
// Duplicate ic rows write bitwise-identical values (benign).
__global__ void k_tsmall(const float* __restrict__ xc, int l) {
    const int off = c_off[l], K = c_K[l], s = c_sc[l];
    const float* Dl = g_Dall + c_doff[l];
    int b = blockIdx.x * blockDim.x + threadIdx.x;
    if (b >= K) return;
    int row = g_ic[blockIdx.y];
    float fs = (float)s, x = xc[row];
    int alo = (int)floorf(fs * x - CUT) + s - 1;
    int ahi = (int)ceilf (fs * x + CUT) + s + 1;
    if (alo < 0) alo = 0;
    if (ahi > K - 1) ahi = K - 1;
    const float* wc = &g_Wc[(size_t)row * RPAD + off];
    float acc = 0.0f;
    for (int a = alo; a <= ahi; ++a)
        acc += wc[a] * Dl[a * K + b];
    g_T[(size_t)row * RPAD + off + b] = acc;
}

// Dense A-operand build for one level (stream s1, after w_dense + D_l).
// block 256 as (64,4); grid ((K+63)/64, NN/4).
__global__ void k_bigT(const float* __restrict__ xc, int l) {
    const int off = c_off[l], K = c_K[l], s = c_sc[l];
    const float* Dl = g_Dall + c_doff[l];
    const int b = blockIdx.x * 64 + (threadIdx.x & 63);
    const int n = blockIdx.y * 4 + (threadIdx.x >> 6);
    if (b >= K) return;
    float fs = (float)s, x = xc[n];
    int alo = (int)floorf(fs * x - CUT) + s - 1;
    int ahi = (int)ceilf (fs * x + CUT) + s + 1;
    if (alo < 0) alo = 0;
    if (ahi > K - 1) ahi = K - 1;
    const float* wc = &g_Wc[(size_t)n * RPAD + off];
    float acc = 0.0f;
    for (int a = alo; a <= ahi; ++a)
        acc += wc[a] * Dl[a * K + b];
    g_Atf[(size_t)n * RPAD + off + b] = __uint_as_float(to_tf32(acc));
}

// ---------------------------------------------------------------------------
// tf32 GEMM with per-tile k-window (byte-identical to the 173.7us version).
// ---------------------------------------------------------------------------
#define TSTAGE 16384
#define TGSMEM (2 * TSTAGE + 256)

__device__ __forceinline__ uint32_t soff(uint32_t r, uint32_t k) {
    return r * 64 + ((((k >> 2) ^ ((r >> 1) & 3)) & 3) << 4) + ((k & 3) << 2);
}
__device__ __forceinline__ uint32_t smem_u32(const void* p) {
    uint32_t a;
    asm("{ .reg .u64 t; cvta.to.shared.u64 t, %1; cvt.u32.u64 %0, t; }"
        : "=r"(a) : "l"(p));
    return a;
}
__device__ __forceinline__ void cp16(uint32_t s, const void* g) {
    asm volatile("cp.async.cg.shared.global [%0], [%1], 16;" :: "r"(s), "l"(g));
}
__device__ __forceinline__ void mma_tf32(float& d0, float& d1, float& d2, float& d3,
                                         uint32_t a0, uint32_t a1, uint32_t a2,
                                         uint32_t a3, uint32_t b0, uint32_t b1) {
    asm volatile(
        "mma.sync.aligned.m16n8k8.row.col.f32.tf32.tf32.f32 "
        "{%0,%1,%2,%3}, {%4,%5,%6,%7}, {%8,%9}, {%0,%1,%2,%3};"
        : "+f"(d0), "+f"(d1), "+f"(d2), "+f"(d3)
        : "r"(a0), "r"(a1), "r"(a2), "r"(a3), "r"(b0), "r"(b1));
}

__global__ __launch_bounds__(256, 2) void k_gemm_tf32(float* __restrict__ C,
                                                      const float* __restrict__ xr) {
    extern __shared__ char smem[];
    const uint32_t sb = smem_u32(smem);
    int* s_list = (int*)(smem + 2 * TSTAGE);
    const int tid  = threadIdx.x;
    const int wid  = tid >> 5, lane = tid & 31;
    const int n0   = blockIdx.y * 128;
    const int m0   = blockIdx.x * 128;
    const int wm   = (wid >> 2) * 64;
    const int wn   = (wid & 3) * 32;

    if (tid == 0) {
        float xmin = xr[m0], xmax = xr[m0 + 127];
        uint32_t mask = 0;
#pragma unroll
        for (int l = 0; l < 5; ++l) {
            int s = c_sc[l];
            float fs = (float)s;
            int lo = c_off[l] + s + (int)floorf(fs * xmin - CUT) - 1;
            int hi = c_off[l] + s + (int)ceilf (fs * xmax + CUT) + 1;
            if (lo < c_off[l]) lo = c_off[l];
            if (hi > c_off[l] + c_K[l] - 1) hi = c_off[l] + c_K[l] - 1;
            if (lo > hi) continue;
            for (int b = (lo >> 4); b <= (hi >> 4); ++b) mask |= (1u << b);
        }
        int nb = 0;
        while (mask) { int b = __ffs(mask) - 1; mask &= mask - 1; s_list[1 + nb++] = b; }
        s_list[0] = nb;
    }
    __syncthreads();
    const int nb = s_list[0];

    float acc[4][4][4];
#pragma unroll
    for (int i = 0; i < 4; ++i)
#pragma unroll
        for (int j = 0; j < 4; ++j)
#pragma unroll
            for (int q = 0; q < 4; ++q) acc[i][j][q] = 0.0f;

    const float* Ab = g_Atf + (size_t)n0 * RPAD;
    const float* Bb = g_Btf + (size_t)m0 * RPAD;

    auto load_chunk = [&](int blk, int stage) {
        const int k0 = blk * 16;
        const uint32_t stb = sb + stage * TSTAGE;
#pragma unroll
        for (int i = 0; i < 4; ++i) {
            int u   = tid + i * 256;
            int arr = u >> 9, rem = u & 511;
            int row = rem >> 2, cq = rem & 3;
            const float* gp = (arr ? Bb : Ab) + (size_t)row * RPAD + k0 + cq * 4;
            cp16(stb + arr * 8192 + row * 64 + (((cq ^ ((row >> 1) & 3)) & 3) << 4), gp);
        }
        asm volatile("cp.async.commit_group;" ::: "memory");
    };

    load_chunk(s_list[1], 0);
    load_chunk(s_list[2], 1);

    const int aq = lane >> 2;
    const int ak = lane & 3;

    for (int c = 0; c < nb; ++c) {
        const int stage = c & 1;
        if (c < nb - 1) asm volatile("cp.async.wait_group 1;" ::: "memory");
        else            asm volatile("cp.async.wait_group 0;" ::: "memory");
        __syncthreads();

        const char* sA = smem + stage * TSTAGE;
        const char* sB = sA + 8192;

#pragma unroll
        for (int ks = 0; ks < 2; ++ks) {
            const int kb = ks * 8;
            uint32_t a[4][4];
#pragma unroll
            for (int mi = 0; mi < 4; ++mi) {
                int r = wm + mi * 16 + aq;
                a[mi][0] = *(const uint32_t*)(sA + soff(r,     kb + ak));
                a[mi][1] = *(const uint32_t*)(sA + soff(r + 8, kb + ak));
                a[mi][2] = *(const uint32_t*)(sA + soff(r,     kb + ak + 4));
                a[mi][3] = *(const uint32_t*)(sA + soff(r + 8, kb + ak + 4));
            }
            uint32_t b[4][2];
#pragma unroll
            for (int nj = 0; nj < 4; ++nj) {
                int r = wn + nj * 8 + aq;
                b[nj][0] = *(const uint32_t*)(sB + soff(r, kb + ak));
                b[nj][1] = *(const uint32_t*)(sB + soff(r, kb + ak + 4));
            }
#pragma unroll
            for (int mi = 0; mi < 4; ++mi)
#pragma unroll
                for (int nj = 0; nj < 4; ++nj)
                    mma_tf32(acc[mi][nj][0], acc[mi][nj][1],
                             acc[mi][nj][2], acc[mi][nj][3],
                             a[mi][0], a[mi][1], a[mi][2], a[mi][3],
                             b[nj][0], b[nj][1]);
        }

        __syncthreads();
        if (c + 2 < nb) load_chunk(s_list[1 + c + 2], stage);
    }

#pragma unroll
    for (int mi = 0; mi < 4; ++mi) {
        int row = n0 + wm + mi * 16 + (lane >> 2);
#pragma unroll
        for (int nj = 0; nj < 4; ++nj) {
            int col = m0 + wn + nj * 8 + (lane & 3) * 2;
            float2* p0 = (float2*)(C + (size_t)row * NN + col);
            float2* p1 = (float2*)(C + (size_t)(row + 8) * NN + col);
            *p0 = make_float2(acc[mi][nj][0], acc[mi][nj][1]);
            *p1 = make_float2(acc[mi][nj][2], acc[mi][nj][3]);
        }
    }
}

// ---------------------------------------------------------------------------
// Fork-join schedule (capture-safe):
//   s0: idx -> smallw -> D0 -> t0 -> D1 -> ... -> D4 -> [join] -> GEMM
//   s1: [fork] w_dense -> (wait D_l) bigT_l for l=0..4
// ---------------------------------------------------------------------------
extern "C" void kernel_launch(void* const* d_in, const int* in_sizes, int n_in,
                              void* d_out, int out_size) {
    const float* img = (const float*)d_in[0];
    const float* xc  = (const float*)d_in[1];
    const float* xr  = (const float*)d_in[2];
    float* out = (float*)d_out;

    (void)in_sizes; (void)n_in; (void)out_size;

    static const int Ks[NLEV] = {17, 33, 65, 129, 257};

    cudaFuncSetAttribute(k_gemm_tf32, cudaFuncAttributeMaxDynamicSharedMemorySize,
                         TGSMEM);

    cudaStream_t s1;
    cudaStreamCreateWithFlags(&s1, cudaStreamNonBlocking);
    cudaEvent_t eFork, eJoin, eD[NLEV];
    cudaEventCreateWithFlags(&eFork, cudaEventDisableTiming);
    cudaEventCreateWithFlags(&eJoin, cudaEventDisableTiming);
    for (int l = 0; l < NLEV; ++l)
        cudaEventCreateWithFlags(&eD[l], cudaEventDisableTiming);

    // fork s1 off the capture stream
    cudaEventRecord(eFork, 0);
    cudaStreamWaitEvent(s1, eFork, 0);

    // s1: dense factors (Wc + tf32 B)
    k_w_dense<<<(NN * RPAD) / 256, 256, 0, s1>>>(xc, xr);

    // s0: serial chain on sample-row subsets
    k_idx<<<2, 256>>>(xc, xr);
    k_smallw<<<(2 * RTOT + 7) / 8, 256>>>(xc, xr);
    for (int l = 0; l < NLEV; ++l) {
        dim3 gD((Ks[l] + 255) / 256, Ks[l]);
        k_D<<<gD, 256>>>(img, xr, l);
        cudaEventRecord(eD[l], 0);
        cudaStreamWaitEvent(s1, eD[l], 0);
        k_bigT<<<dim3((Ks[l] + 63) / 64, NN / 4), 256, 0, s1>>>(xc, l);
        if (l < NLEV - 1) {
            dim3 gt((Ks[l] + 255) / 256, RTOT);
            k_tsmall<<<gt, 256>>>(xc, l);
        }
    }

    // join s1 back, then GEMM
    cudaEventRecord(eJoin, s1);
    cudaStreamWaitEvent(0, eJoin, 0);
    dim3 gg(NN / 128, NN / 128);
    k_gemm_tf32<<<gg, 256, TGSMEM>>>(out, xr);
}